// round 8
// baseline (speedup 1.0000x reference)
#include <cuda_runtime.h>
#include <cuda_bf16.h>
#include <math.h>

#define N_NODES 100000
#define N_EDGES 1600000
#define HID     128
#define NGRAPH  256

typedef unsigned long long ull;

// ---------------- scratch (device globals; no allocation anywhere) ---------
__device__ float g_A[(size_t)N_NODES * HID];      // h0 -> (layer2 agg) -> h2
__device__ float g_B[(size_t)N_NODES * HID];      // layer1 agg -> h1
__device__ float g_pooled[NGRAPH * HID];
__device__ float g_counts[NGRAPH];

// ---------------- helpers --------------------------------------------------
__device__ __forceinline__ void red_add_v4(float* addr, float4 v) {
    asm volatile("red.global.add.v4.f32 [%0], {%1,%2,%3,%4};"
                 :: "l"(__cvta_generic_to_global(addr)),
                    "f"(v.x), "f"(v.y), "f"(v.z), "f"(v.w)
                 : "memory");
}

// packed f32x2 FMA: d = a*b + c elementwise on (lo,hi) pairs
__device__ __forceinline__ ull ffma2(ull a, ull b, ull c) {
    ull d;
    asm("fma.rn.f32x2 %0, %1, %2, %3;" : "=l"(d) : "l"(a), "l"(b), "l"(c));
    return d;
}

// ---------------- 0a. zero a node-feature buffer ---------------------------
__global__ void zero_buf_kernel(int which)
{
    float4* p = (float4*)(which ? g_B : g_A);
    p[(size_t)blockIdx.x * 256 + threadIdx.x] = make_float4(0.f, 0.f, 0.f, 0.f);
}

// zero pooled sums + counts
__global__ void zero_pool_kernel()
{
    int idx = blockIdx.x * 256 + threadIdx.x;
    if (idx < NGRAPH * HID) g_pooled[idx] = 0.f;
    else                    g_counts[idx - NGRAPH * HID] = 0.f;
}

// ---------------- 1. embedding with max_norm=1 -----------------------------
__global__ void embed_kernel(const int* __restrict__ x,
                             const float* __restrict__ emb_w)
{
    int node = (blockIdx.x * 256 + threadIdx.x) >> 5;
    int lane = threadIdx.x & 31;
    int idx  = x[node];
    float4 v = *(const float4*)&emb_w[(size_t)idx * HID + lane * 4];
    float ss = v.x * v.x + v.y * v.y + v.z * v.z + v.w * v.w;
    #pragma unroll
    for (int o = 16; o > 0; o >>= 1)
        ss += __shfl_xor_sync(0xffffffffu, ss, o);
    float scale = fminf(1.0f, 1.0f / (sqrtf(ss) + 1e-7f));
    v.x *= scale; v.y *= scale; v.z *= scale; v.w *= scale;
    *(float4*)&g_A[(size_t)node * HID + lane * 4] = v;
}

// ---------------- 2. per-edge gather * w -> scatter-add --------------------
__global__ void __launch_bounds__(256)
edge_kernel(const int* __restrict__ ei,
            const float* __restrict__ ew,
            int layer)
{
    const float* h = layer ? g_B : g_A;
    float*     agg = layer ? g_A : g_B;
    int warp = (blockIdx.x * 256 + threadIdx.x) >> 5;
    int lane = threadIdx.x & 31;
    int e0 = warp * 2;
    int e1 = e0 + 1;

    int   src0 = ei[e0],           src1 = ei[e1];
    int   dst0 = ei[N_EDGES + e0], dst1 = ei[N_EDGES + e1];
    float w0   = ew[e0],           w1   = ew[e1];

    float4 v0 = *(const float4*)&h[(size_t)src0 * HID + lane * 4];
    float4 v1 = *(const float4*)&h[(size_t)src1 * HID + lane * 4];
    v0.x *= w0; v0.y *= w0; v0.z *= w0; v0.w *= w0;
    v1.x *= w1; v1.y *= w1; v1.z *= w1; v1.w *= w1;
    red_add_v4(&agg[(size_t)dst0 * HID + lane * 4], v0);
    red_add_v4(&agg[(size_t)dst1 * HID + lane * 4], v1);
}

// ---------------- 3. node update via packed f32x2 FMA ----------------------
// relu(agg@Wr^T + b + h@Wo^T). 32-node tiles (grid 3125 EXACT), 256 threads.
// thread -> cols {jq, jq+32, jq+64, jq+96} x nodes ng*4..ng*4+3.
// acc[4][4] ull = 64 regs -> ~90 total -> 2 blocks (16 warps) per SM.
// Accumulators packed over K parity: acc = (sum even k, sum odd k).
// Weights used in ORIGINAL [j][k] layout -> (w[j][2q], w[j][2q+1]) is one ull.
// SMEM: features 32x128 f32 = 16KB + weight chunk 16x128 ull = 16KB = 32KB.
#define KCHUNK 16   // k-pairs per weight stage (16 pairs = 32 k)
__global__ void __launch_bounds__(256, 2)
node_kernel(int layer, const float* __restrict__ w_rel,
            const float* __restrict__ w_root,
            const float* __restrict__ bias)
{
    __shared__ float sF[32 * 128];     // feature tile (agg, then h, then out)
    __shared__ ull   wS[KCHUNK * 128]; // weight chunk: [k-pair][j]

    const float* agg = layer ? g_A : g_B;
    const float* h   = layer ? g_B : g_A;
    float*       out = layer ? g_A : g_B;

    int tid = threadIdx.x;
    int jq  = tid & 31;
    int ng  = tid >> 5;                // 0..7 -> nodes ng*4..ng*4+3
    size_t base = (size_t)blockIdx.x * 32;

    ull acc[4][4];
    #pragma unroll
    for (int n = 0; n < 4; n++)
        #pragma unroll
        for (int m = 0; m < 4; m++) acc[n][m] = 0ull;

    #pragma unroll
    for (int pass = 0; pass < 2; pass++) {
        const float* feat = pass ? h : agg;
        const ull*   w64  = (const ull*)(pass ? w_root : w_rel); // [j][64 k-pairs]

        // stage feature tile: 32 nodes x 32 float4 (exact, no bounds checks)
        __syncthreads();
        #pragma unroll
        for (int i = tid; i < 32 * 32; i += 256)
            ((float4*)sF)[i] = *(const float4*)&feat[(base + (i >> 5)) * HID + (i & 31) * 4];

        for (int chunk = 0; chunk < 64 / KCHUNK; chunk++) {
            __syncthreads();
            // stage weight chunk: wS[q][j] = w64[j*64 + chunk*KCHUNK + q]
            #pragma unroll
            for (int i = tid; i < KCHUNK * 128; i += 256) {
                int j = i >> 4, q = i & (KCHUNK - 1);
                wS[q * 128 + j] = w64[(size_t)j * 64 + chunk * KCHUNK + q];
            }
            __syncthreads();

            #pragma unroll
            for (int q = 0; q < KCHUNK; q++) {
                ull w2[4];
                #pragma unroll
                for (int m = 0; m < 4; m++)
                    w2[m] = wS[q * 128 + jq + 32 * m];
                #pragma unroll
                for (int n = 0; n < 4; n++) {
                    ull a2 = *(const ull*)&sF[(ng * 4 + n) * 128 +
                                              chunk * (2 * KCHUNK) + 2 * q];
                    #pragma unroll
                    for (int m = 0; m < 4; m++)
                        acc[n][m] = ffma2(a2, w2[m], acc[n][m]);
                }
            }
        }
    }

    // fold parity halves + bias + relu, stage into sF[node][col]
    float b4[4];
    #pragma unroll
    for (int m = 0; m < 4; m++) b4[m] = __ldg(&bias[jq + 32 * m]);

    __syncthreads();
    #pragma unroll
    for (int n = 0; n < 4; n++) {
        int node = ng * 4 + n;
        #pragma unroll
        for (int m = 0; m < 4; m++) {
            unsigned int lo, hi;
            asm("mov.b64 {%0, %1}, %2;" : "=r"(lo), "=r"(hi) : "l"(acc[n][m]));
            float v = __uint_as_float(lo) + __uint_as_float(hi) + b4[m];
            sF[node * 128 + jq + 32 * m] = fmaxf(v, 0.f);
        }
    }
    __syncthreads();

    // coalesced float4 write-out (exact)
    #pragma unroll
    for (int i = tid; i < 32 * 32; i += 256)
        *(float4*)&out[(base + (i >> 5)) * HID + (i & 31) * 4] = ((float4*)sF)[i];
}

// ---------------- 4. mean pool (sums + counts) -----------------------------
__global__ void pool_kernel(const int* __restrict__ batch)
{
    int node = (blockIdx.x * 256 + threadIdx.x) >> 5;
    int lane = threadIdx.x & 31;
    int g = batch[node];
    float4 v = *(const float4*)&g_A[(size_t)node * HID + lane * 4];
    red_add_v4(&g_pooled[(size_t)g * HID + lane * 4], v);
    if (lane == 0) atomicAdd(&g_counts[g], 1.0f);
}

// ---------------- 5. classifier + softmax ----------------------------------
__global__ void cls_kernel(const float* __restrict__ w1,  // [64][128]
                           const float* __restrict__ b1,  // [64]
                           const float* __restrict__ w2,  // [2][64]
                           const float* __restrict__ b2,  // [2]
                           float* __restrict__ out)       // [256][2]
{
    int g = blockIdx.x;
    int j = threadIdx.x;                 // 0..63
    __shared__ float p[128];
    __shared__ float z[64];
    float inv = 1.0f / fmaxf(g_counts[g], 1.0f);
    p[j]      = g_pooled[g * HID + j] * inv;
    p[j + 64] = g_pooled[g * HID + j + 64] * inv;
    __syncthreads();
    float acc = b1[j];
    #pragma unroll 4
    for (int k = 0; k < 128; k++)
        acc += p[k] * w1[j * 128 + k];
    z[j] = fmaxf(acc, 0.f);
    __syncthreads();
    if (j == 0) {
        float l0 = b2[0], l1 = b2[1];
        #pragma unroll 4
        for (int k = 0; k < 64; k++) {
            l0 += z[k] * w2[k];
            l1 += z[k] * w2[64 + k];
        }
        float m  = fmaxf(l0, l1);
        float e0 = expf(l0 - m), e1 = expf(l1 - m);
        float s  = e0 + e1;
        out[g * 2]     = e0 / s;
        out[g * 2 + 1] = e1 / s;
    }
}

// ---------------- launch: KERNEL LAUNCHES ONLY ------------------------------
extern "C" void kernel_launch(void* const* d_in, const int* in_sizes, int n_in,
                              void* d_out, int out_size)
{
    const int*   x      = (const int*)  d_in[0];
    const int*   ei     = (const int*)  d_in[1];
    const float* ew     = (const float*)d_in[2];
    const int*   batch  = (const int*)  d_in[3];
    const float* emb_w  = (const float*)d_in[4];
    const float* w1_rel = (const float*)d_in[5];
    const float* b1_rel = (const float*)d_in[6];
    const float* w1_root= (const float*)d_in[7];
    const float* w2_rel = (const float*)d_in[8];
    const float* b2_rel = (const float*)d_in[9];
    const float* w2_root= (const float*)d_in[10];
    const float* cls1_w = (const float*)d_in[11];
    const float* cls1_b = (const float*)d_in[12];
    const float* cls2_w = (const float*)d_in[13];
    const float* cls2_b = (const float*)d_in[14];
    float* out = (float*)d_out;

    const int nodeTiles = N_NODES / 32;   // 3125 exact

    // embedding -> A
    embed_kernel<<<12500, 256>>>(x, emb_w);

    // layer 1: agg in B, h1 written in-place into B
    zero_buf_kernel<<<12500, 256>>>(1);
    edge_kernel<<<100000, 256>>>(ei, ew, 0);
    node_kernel<<<nodeTiles, 256>>>(0, w1_rel, w1_root, b1_rel);

    // layer 2: agg in A (h0 dead), h2 written in-place into A
    zero_buf_kernel<<<12500, 256>>>(0);
    edge_kernel<<<100000, 256>>>(ei, ew, 1);
    node_kernel<<<nodeTiles, 256>>>(1, w2_rel, w2_root, b2_rel);

    // pooling
    zero_pool_kernel<<<129, 256>>>();
    pool_kernel<<<12500, 256>>>(batch);

    // classifier + softmax
    cls_kernel<<<NGRAPH, 64>>>(cls1_w, cls1_b, cls2_w, cls2_b, out);
}

// round 9
// speedup vs baseline: 1.2023x; 1.2023x over previous
#include <cuda_runtime.h>
#include <cuda_bf16.h>
#include <math.h>

#define N_NODES 100000
#define N_EDGES 1600000
#define HID     128
#define NGRAPH  256

typedef unsigned long long ull;

// ---------------- scratch (device globals; no allocation anywhere) ---------
__device__ float g_A[(size_t)N_NODES * HID];      // h0 -> (layer2 agg) -> h2
__device__ float g_B[(size_t)N_NODES * HID];      // layer1 agg -> h1
__device__ float g_pooled[NGRAPH * HID];
__device__ float g_counts[NGRAPH];

// ---------------- helpers --------------------------------------------------
__device__ __forceinline__ void red_add_v4(float* addr, float4 v) {
    asm volatile("red.global.add.v4.f32 [%0], {%1,%2,%3,%4};"
                 :: "l"(__cvta_generic_to_global(addr)),
                    "f"(v.x), "f"(v.y), "f"(v.z), "f"(v.w)
                 : "memory");
}

// packed f32x2 FMA: d = a*b + c elementwise on (lo,hi) pairs
__device__ __forceinline__ ull ffma2(ull a, ull b, ull c) {
    ull d;
    asm("fma.rn.f32x2 %0, %1, %2, %3;" : "=l"(d) : "l"(a), "l"(b), "l"(c));
    return d;
}

// ---------------- 0a. zero a node-feature buffer ---------------------------
__global__ void zero_buf_kernel(int which)
{
    float4* p = (float4*)(which ? g_B : g_A);
    p[(size_t)blockIdx.x * 256 + threadIdx.x] = make_float4(0.f, 0.f, 0.f, 0.f);
}

// zero pooled sums + counts
__global__ void zero_pool_kernel()
{
    int idx = blockIdx.x * 256 + threadIdx.x;
    if (idx < NGRAPH * HID) g_pooled[idx] = 0.f;
    else                    g_counts[idx - NGRAPH * HID] = 0.f;
}

// ---------------- 1. embedding with max_norm=1 -----------------------------
__global__ void embed_kernel(const int* __restrict__ x,
                             const float* __restrict__ emb_w)
{
    int node = (blockIdx.x * 256 + threadIdx.x) >> 5;
    int lane = threadIdx.x & 31;
    int idx  = x[node];
    float4 v = *(const float4*)&emb_w[(size_t)idx * HID + lane * 4];
    float ss = v.x * v.x + v.y * v.y + v.z * v.z + v.w * v.w;
    #pragma unroll
    for (int o = 16; o > 0; o >>= 1)
        ss += __shfl_xor_sync(0xffffffffu, ss, o);
    float scale = fminf(1.0f, 1.0f / (sqrtf(ss) + 1e-7f));
    v.x *= scale; v.y *= scale; v.z *= scale; v.w *= scale;
    *(float4*)&g_A[(size_t)node * HID + lane * 4] = v;
}

// ---------------- 2. per-edge gather * w -> scatter-add --------------------
__global__ void __launch_bounds__(256)
edge_kernel(const int* __restrict__ ei,
            const float* __restrict__ ew,
            int layer)
{
    const float* h = layer ? g_B : g_A;
    float*     agg = layer ? g_A : g_B;
    int warp = (blockIdx.x * 256 + threadIdx.x) >> 5;
    int lane = threadIdx.x & 31;
    int e0 = warp * 2;
    int e1 = e0 + 1;

    int   src0 = ei[e0],           src1 = ei[e1];
    int   dst0 = ei[N_EDGES + e0], dst1 = ei[N_EDGES + e1];
    float w0   = ew[e0],           w1   = ew[e1];

    float4 v0 = *(const float4*)&h[(size_t)src0 * HID + lane * 4];
    float4 v1 = *(const float4*)&h[(size_t)src1 * HID + lane * 4];
    v0.x *= w0; v0.y *= w0; v0.z *= w0; v0.w *= w0;
    v1.x *= w1; v1.y *= w1; v1.z *= w1; v1.w *= w1;
    red_add_v4(&agg[(size_t)dst0 * HID + lane * 4], v0);
    red_add_v4(&agg[(size_t)dst1 * HID + lane * 4], v1);
}

// ---------------- 3. node update via packed f32x2 FMA ----------------------
// relu(agg@Wr^T + b + h@Wo^T). 32-node tiles (grid 3125 EXACT), 128 threads.
// 4 warps; thread -> nodes ng*8..+7 (ng=tid>>5) x cols {jq+32m} (jq=tid&31).
// acc[8][4] ull = 64 f32 regs; __launch_bounds__(128,4) -> 16 warps/SM.
// Crossbar/FMA rebalance: per 2 k-pairs/warp = 8 w2 LDS.64 (16 cyc) +
// 8 a2 broadcast LDS.128 (8 cyc) vs 64 FFMA2 (128 SMSP-cyc) -> FMA-bound.
// SMEM: sF 32x128 f32 = 16KB + wS 8x128 ull = 8KB -> 24KB/block.
#define KCHUNK 8    // k-pairs per weight stage (8 pairs = 16 k)
__global__ void __launch_bounds__(128, 4)
node_kernel(int layer, const float* __restrict__ w_rel,
            const float* __restrict__ w_root,
            const float* __restrict__ bias)
{
    __shared__ float sF[32 * 128];     // feature tile (agg, then h, then out)
    __shared__ ull   wS[KCHUNK * 128]; // weight chunk: [k-pair][j]

    const float* agg = layer ? g_A : g_B;
    const float* h   = layer ? g_B : g_A;
    float*       out = layer ? g_A : g_B;

    int tid = threadIdx.x;
    int jq  = tid & 31;
    int ng  = tid >> 5;                // 0..3 -> nodes ng*8..ng*8+7
    size_t base = (size_t)blockIdx.x * 32;

    ull acc[8][4];
    #pragma unroll
    for (int n = 0; n < 8; n++)
        #pragma unroll
        for (int m = 0; m < 4; m++) acc[n][m] = 0ull;

    #pragma unroll
    for (int pass = 0; pass < 2; pass++) {
        const float* feat = pass ? h : agg;
        const ull*   w64  = (const ull*)(pass ? w_root : w_rel); // [j][64 k-pairs]

        // stage feature tile: 32 nodes x 32 float4 (exact)
        __syncthreads();
        #pragma unroll
        for (int i = tid; i < 32 * 32; i += 128)
            ((float4*)sF)[i] = *(const float4*)&feat[(base + (i >> 5)) * HID + (i & 31) * 4];

        for (int chunk = 0; chunk < 64 / KCHUNK; chunk++) {
            __syncthreads();
            // stage weight chunk: wS[q][j] = w64[j*64 + chunk*KCHUNK + q]
            #pragma unroll
            for (int i = tid; i < KCHUNK * 128; i += 128) {
                int j = i >> 3, q = i & (KCHUNK - 1);
                wS[q * 128 + j] = w64[(size_t)j * 64 + chunk * KCHUNK + q];
            }
            __syncthreads();

            // qq iterates pairs-of-k-pairs: a2 loaded 16B (4 k) at a time
            #pragma unroll
            for (int qq = 0; qq < KCHUNK / 2; qq++) {
                ull w2a[4], w2b[4];
                #pragma unroll
                for (int m = 0; m < 4; m++) {
                    w2a[m] = wS[(2 * qq)     * 128 + jq + 32 * m];
                    w2b[m] = wS[(2 * qq + 1) * 128 + jq + 32 * m];
                }
                #pragma unroll
                for (int n = 0; n < 8; n++) {
                    // broadcast 16B: k floats [chunk*16 + qq*4 .. +3]
                    ulonglong2 a4 = *(const ulonglong2*)
                        &sF[(ng * 8 + n) * 128 + chunk * (2 * KCHUNK) + 4 * qq];
                    #pragma unroll
                    for (int m = 0; m < 4; m++)
                        acc[n][m] = ffma2(a4.x, w2a[m], acc[n][m]);
                    #pragma unroll
                    for (int m = 0; m < 4; m++)
                        acc[n][m] = ffma2(a4.y, w2b[m], acc[n][m]);
                }
            }
        }
    }

    // fold parity halves + bias + relu, stage into sF[node][col]
    float b4[4];
    #pragma unroll
    for (int m = 0; m < 4; m++) b4[m] = __ldg(&bias[jq + 32 * m]);

    __syncthreads();
    #pragma unroll
    for (int n = 0; n < 8; n++) {
        int node = ng * 8 + n;
        #pragma unroll
        for (int m = 0; m < 4; m++) {
            unsigned int lo, hi;
            asm("mov.b64 {%0, %1}, %2;" : "=r"(lo), "=r"(hi) : "l"(acc[n][m]));
            float v = __uint_as_float(lo) + __uint_as_float(hi) + b4[m];
            sF[node * 128 + jq + 32 * m] = fmaxf(v, 0.f);
        }
    }
    __syncthreads();

    // coalesced float4 write-out (exact)
    #pragma unroll
    for (int i = tid; i < 32 * 32; i += 128)
        *(float4*)&out[(base + (i >> 5)) * HID + (i & 31) * 4] = ((float4*)sF)[i];
}

// ---------------- 4. mean pool (sums + counts) -----------------------------
__global__ void pool_kernel(const int* __restrict__ batch)
{
    int node = (blockIdx.x * 256 + threadIdx.x) >> 5;
    int lane = threadIdx.x & 31;
    int g = batch[node];
    float4 v = *(const float4*)&g_A[(size_t)node * HID + lane * 4];
    red_add_v4(&g_pooled[(size_t)g * HID + lane * 4], v);
    if (lane == 0) atomicAdd(&g_counts[g], 1.0f);
}

// ---------------- 5. classifier + softmax ----------------------------------
__global__ void cls_kernel(const float* __restrict__ w1,  // [64][128]
                           const float* __restrict__ b1,  // [64]
                           const float* __restrict__ w2,  // [2][64]
                           const float* __restrict__ b2,  // [2]
                           float* __restrict__ out)       // [256][2]
{
    int g = blockIdx.x;
    int j = threadIdx.x;                 // 0..63
    __shared__ float p[128];
    __shared__ float z[64];
    float inv = 1.0f / fmaxf(g_counts[g], 1.0f);
    p[j]      = g_pooled[g * HID + j] * inv;
    p[j + 64] = g_pooled[g * HID + j + 64] * inv;
    __syncthreads();
    float acc = b1[j];
    #pragma unroll 4
    for (int k = 0; k < 128; k++)
        acc += p[k] * w1[j * 128 + k];
    z[j] = fmaxf(acc, 0.f);
    __syncthreads();
    if (j == 0) {
        float l0 = b2[0], l1 = b2[1];
        #pragma unroll 4
        for (int k = 0; k < 64; k++) {
            l0 += z[k] * w2[k];
            l1 += z[k] * w2[64 + k];
        }
        float m  = fmaxf(l0, l1);
        float e0 = expf(l0 - m), e1 = expf(l1 - m);
        float s  = e0 + e1;
        out[g * 2]     = e0 / s;
        out[g * 2 + 1] = e1 / s;
    }
}

// ---------------- launch: KERNEL LAUNCHES ONLY ------------------------------
extern "C" void kernel_launch(void* const* d_in, const int* in_sizes, int n_in,
                              void* d_out, int out_size)
{
    const int*   x      = (const int*)  d_in[0];
    const int*   ei     = (const int*)  d_in[1];
    const float* ew     = (const float*)d_in[2];
    const int*   batch  = (const int*)  d_in[3];
    const float* emb_w  = (const float*)d_in[4];
    const float* w1_rel = (const float*)d_in[5];
    const float* b1_rel = (const float*)d_in[6];
    const float* w1_root= (const float*)d_in[7];
    const float* w2_rel = (const float*)d_in[8];
    const float* b2_rel = (const float*)d_in[9];
    const float* w2_root= (const float*)d_in[10];
    const float* cls1_w = (const float*)d_in[11];
    const float* cls1_b = (const float*)d_in[12];
    const float* cls2_w = (const float*)d_in[13];
    const float* cls2_b = (const float*)d_in[14];
    float* out = (float*)d_out;

    const int nodeTiles = N_NODES / 32;   // 3125 exact

    // embedding -> A
    embed_kernel<<<12500, 256>>>(x, emb_w);

    // layer 1: agg in B, h1 written in-place into B
    zero_buf_kernel<<<12500, 256>>>(1);
    edge_kernel<<<100000, 256>>>(ei, ew, 0);
    node_kernel<<<nodeTiles, 128>>>(0, w1_rel, w1_root, b1_rel);

    // layer 2: agg in A (h0 dead), h2 written in-place into A
    zero_buf_kernel<<<12500, 256>>>(0);
    edge_kernel<<<100000, 256>>>(ei, ew, 1);
    node_kernel<<<nodeTiles, 128>>>(1, w2_rel, w2_root, b2_rel);

    // pooling
    zero_pool_kernel<<<129, 256>>>();
    pool_kernel<<<12500, 256>>>(batch);

    // classifier + softmax
    cls_kernel<<<NGRAPH, 64>>>(cls1_w, cls1_b, cls2_w, cls2_b, out);
}

// round 16
// speedup vs baseline: 1.9929x; 1.6576x over previous
#include <cuda_runtime.h>
#include <cuda_bf16.h>
#include <math.h>

#define N_NODES 100000
#define N_EDGES 1600000
#define HID     128
#define NGRAPH  256

typedef unsigned long long ull;

// ---------------- scratch (device globals; no allocation anywhere) ---------
__device__ float g_A[(size_t)N_NODES * HID];      // h0 -> (layer2 agg) -> h2
__device__ float g_B[(size_t)N_NODES * HID];      // layer1 agg -> h1
__device__ float g_pooled[NGRAPH * HID];
__device__ float g_counts[NGRAPH];

// ---------------- helpers --------------------------------------------------
__device__ __forceinline__ void red_add_v4(float* addr, float4 v) {
    asm volatile("red.global.add.v4.f32 [%0], {%1,%2,%3,%4};"
                 :: "l"(__cvta_generic_to_global(addr)),
                    "f"(v.x), "f"(v.y), "f"(v.z), "f"(v.w)
                 : "memory");
}

__device__ __forceinline__ unsigned int f2tf32(float f) {
    unsigned int r;
    asm("cvt.rna.tf32.f32 %0, %1;" : "=r"(r) : "f"(f));
    return r;
}

// ---------------- 0a. zero a node-feature buffer ---------------------------
__global__ void zero_buf_kernel(int which)
{
    float4* p = (float4*)(which ? g_B : g_A);
    p[(size_t)blockIdx.x * 256 + threadIdx.x] = make_float4(0.f, 0.f, 0.f, 0.f);
}

// zero pooled sums + counts
__global__ void zero_pool_kernel()
{
    int idx = blockIdx.x * 256 + threadIdx.x;
    if (idx < NGRAPH * HID) g_pooled[idx] = 0.f;
    else                    g_counts[idx - NGRAPH * HID] = 0.f;
}

// ---------------- 1. embedding with max_norm=1 -----------------------------
__global__ void embed_kernel(const int* __restrict__ x,
                             const float* __restrict__ emb_w)
{
    int node = (blockIdx.x * 256 + threadIdx.x) >> 5;
    int lane = threadIdx.x & 31;
    int idx  = x[node];
    float4 v = *(const float4*)&emb_w[(size_t)idx * HID + lane * 4];
    float ss = v.x * v.x + v.y * v.y + v.z * v.z + v.w * v.w;
    #pragma unroll
    for (int o = 16; o > 0; o >>= 1)
        ss += __shfl_xor_sync(0xffffffffu, ss, o);
    float scale = fminf(1.0f, 1.0f / (sqrtf(ss) + 1e-7f));
    v.x *= scale; v.y *= scale; v.z *= scale; v.w *= scale;
    *(float4*)&g_A[(size_t)node * HID + lane * 4] = v;
}

// ---------------- 2. per-edge gather * w -> scatter-add --------------------
__global__ void __launch_bounds__(256)
edge_kernel(const int* __restrict__ ei,
            const float* __restrict__ ew,
            int layer)
{
    const float* h = layer ? g_B : g_A;
    float*     agg = layer ? g_A : g_B;
    int warp = (blockIdx.x * 256 + threadIdx.x) >> 5;
    int lane = threadIdx.x & 31;
    int e0 = warp * 2;
    int e1 = e0 + 1;

    int   src0 = ei[e0],           src1 = ei[e1];
    int   dst0 = ei[N_EDGES + e0], dst1 = ei[N_EDGES + e1];
    float w0   = ew[e0],           w1   = ew[e1];

    float4 v0 = *(const float4*)&h[(size_t)src0 * HID + lane * 4];
    float4 v1 = *(const float4*)&h[(size_t)src1 * HID + lane * 4];
    v0.x *= w0; v0.y *= w0; v0.z *= w0; v0.w *= w0;
    v1.x *= w1; v1.y *= w1; v1.z *= w1; v1.w *= w1;
    red_add_v4(&agg[(size_t)dst0 * HID + lane * 4], v0);
    red_add_v4(&agg[(size_t)dst1 * HID + lane * 4], v1);
}

// ---------------- 3. node update via tf32 mma.sync -------------------------
// out[n] = relu([agg[n] | h[n]] @ [Wr|Wo]^T + b): [100k x 256] x [256 x 128].
// Block tile: 64 nodes x 128 cols, 256 thr (8 warps).
// Warp (wy = warp>>1, wx = warp&1): 16 nodes (wy*16) x 64 cols (wx*64)
//  = 8 mma.m16n8k8 tiles, acc = 8x4 = 32 f32 regs.
// K = 256 staged in 8 chunks of 32 (chunks 0-3: agg/w_rel, 4-7: h/w_root),
// tf32-rounded at staging. Pitch 36 floats -> conflict-free fragment LDS.
// SMEM: sA 64x36 + sB 128x36 + bias = ~28KB static.
__global__ void __launch_bounds__(256)
node_kernel(int layer, const float* __restrict__ w_rel,
            const float* __restrict__ w_root,
            const float* __restrict__ bias)
{
    __shared__ unsigned int sA[64 * 36];
    __shared__ unsigned int sB[128 * 36];
    __shared__ float sBias[128];

    const float* agg = layer ? g_A : g_B;
    const float* h   = layer ? g_B : g_A;
    float*       out = layer ? g_A : g_B;

    int tid  = threadIdx.x;
    int warp = tid >> 5;
    int lane = tid & 31;
    int wy   = warp >> 1;          // node group (16 nodes)
    int wx   = warp & 1;           // col half (64 cols)
    int gid  = lane >> 2;          // 0..7
    int tig  = lane & 3;           // 0..3

    if (tid < 128) sBias[tid] = bias[tid];

    size_t base = (size_t)blockIdx.x * 64;

    float acc[8][4];
    #pragma unroll
    for (int t = 0; t < 8; t++)
        #pragma unroll
        for (int c = 0; c < 4; c++) acc[t][c] = 0.f;

    #pragma unroll
    for (int chunk = 0; chunk < 8; chunk++) {
        const float* feat = (chunk < 4) ? agg : h;
        const float* w    = (chunk < 4) ? w_rel : w_root;
        int kofs = (chunk & 3) * 32;

        __syncthreads();
        // stage A: 64 nodes x 8 float4 (clamped reads; writes masked later)
        #pragma unroll
        for (int i = tid; i < 512; i += 256) {
            int row = i >> 3, c4 = i & 7;
            size_t gn = base + row;
            if (gn >= N_NODES) gn = N_NODES - 1;
            float4 v = *(const float4*)&feat[gn * HID + kofs + c4 * 4];
            unsigned int* d = &sA[row * 36 + c4 * 4];
            d[0] = f2tf32(v.x); d[1] = f2tf32(v.y);
            d[2] = f2tf32(v.z); d[3] = f2tf32(v.w);
        }
        // stage B: 128 rows (out cols) x 8 float4
        #pragma unroll
        for (int i = tid; i < 1024; i += 256) {
            int row = i >> 3, c4 = i & 7;
            float4 v = *(const float4*)&w[(size_t)row * HID + kofs + c4 * 4];
            unsigned int* d = &sB[row * 36 + c4 * 4];
            d[0] = f2tf32(v.x); d[1] = f2tf32(v.y);
            d[2] = f2tf32(v.z); d[3] = f2tf32(v.w);
        }
        __syncthreads();

        #pragma unroll
        for (int ks = 0; ks < 32; ks += 8) {
            unsigned int a0 = sA[(wy * 16 + gid)     * 36 + ks + tig];
            unsigned int a1 = sA[(wy * 16 + gid + 8) * 36 + ks + tig];
            unsigned int a2 = sA[(wy * 16 + gid)     * 36 + ks + tig + 4];
            unsigned int a3 = sA[(wy * 16 + gid + 8) * 36 + ks + tig + 4];
            #pragma unroll
            for (int t = 0; t < 8; t++) {
                int col = wx * 64 + t * 8;
                unsigned int b0 = sB[(col + gid) * 36 + ks + tig];
                unsigned int b1 = sB[(col + gid) * 36 + ks + tig + 4];
                asm("mma.sync.aligned.m16n8k8.row.col.f32.tf32.tf32.f32 "
                    "{%0,%1,%2,%3}, {%4,%5,%6,%7}, {%8,%9}, {%0,%1,%2,%3};"
                    : "+f"(acc[t][0]), "+f"(acc[t][1]),
                      "+f"(acc[t][2]), "+f"(acc[t][3])
                    : "r"(a0), "r"(a1), "r"(a2), "r"(a3), "r"(b0), "r"(b1));
            }
        }
    }

    // epilogue: bias + relu, direct float2 stores (row-masked)
    size_t r0 = base + wy * 16 + gid;
    size_t r1 = r0 + 8;
    #pragma unroll
    for (int t = 0; t < 8; t++) {
        int col = wx * 64 + t * 8 + tig * 2;
        float bx = sBias[col], by = sBias[col + 1];
        if (r0 < N_NODES) {
            float2 o;
            o.x = fmaxf(acc[t][0] + bx, 0.f);
            o.y = fmaxf(acc[t][1] + by, 0.f);
            *(float2*)&out[r0 * HID + col] = o;
        }
        if (r1 < N_NODES) {
            float2 o;
            o.x = fmaxf(acc[t][2] + bx, 0.f);
            o.y = fmaxf(acc[t][3] + by, 0.f);
            *(float2*)&out[r1 * HID + col] = o;
        }
    }
}

// ---------------- 4. mean pool (sums + counts) -----------------------------
__global__ void pool_kernel(const int* __restrict__ batch)
{
    int node = (blockIdx.x * 256 + threadIdx.x) >> 5;
    int lane = threadIdx.x & 31;
    int g = batch[node];
    float4 v = *(const float4*)&g_A[(size_t)node * HID + lane * 4];
    red_add_v4(&g_pooled[(size_t)g * HID + lane * 4], v);
    if (lane == 0) atomicAdd(&g_counts[g], 1.0f);
}

// ---------------- 5. classifier + softmax ----------------------------------
__global__ void cls_kernel(const float* __restrict__ w1,  // [64][128]
                           const float* __restrict__ b1,  // [64]
                           const float* __restrict__ w2,  // [2][64]
                           const float* __restrict__ b2,  // [2]
                           float* __restrict__ out)       // [256][2]
{
    int g = blockIdx.x;
    int j = threadIdx.x;                 // 0..63
    __shared__ float p[128];
    __shared__ float z[64];
    float inv = 1.0f / fmaxf(g_counts[g], 1.0f);
    p[j]      = g_pooled[g * HID + j] * inv;
    p[j + 64] = g_pooled[g * HID + j + 64] * inv;
    __syncthreads();
    float acc = b1[j];
    #pragma unroll 4
    for (int k = 0; k < 128; k++)
        acc += p[k] * w1[j * 128 + k];
    z[j] = fmaxf(acc, 0.f);
    __syncthreads();
    if (j == 0) {
        float l0 = b2[0], l1 = b2[1];
        #pragma unroll 4
        for (int k = 0; k < 64; k++) {
            l0 += z[k] * w2[k];
            l1 += z[k] * w2[64 + k];
        }
        float m  = fmaxf(l0, l1);
        float e0 = expf(l0 - m), e1 = expf(l1 - m);
        float s  = e0 + e1;
        out[g * 2]     = e0 / s;
        out[g * 2 + 1] = e1 / s;
    }
}

// ---------------- launch: KERNEL LAUNCHES ONLY ------------------------------
extern "C" void kernel_launch(void* const* d_in, const int* in_sizes, int n_in,
                              void* d_out, int out_size)
{
    const int*   x      = (const int*)  d_in[0];
    const int*   ei     = (const int*)  d_in[1];
    const float* ew     = (const float*)d_in[2];
    const int*   batch  = (const int*)  d_in[3];
    const float* emb_w  = (const float*)d_in[4];
    const float* w1_rel = (const float*)d_in[5];
    const float* b1_rel = (const float*)d_in[6];
    const float* w1_root= (const float*)d_in[7];
    const float* w2_rel = (const float*)d_in[8];
    const float* b2_rel = (const float*)d_in[9];
    const float* w2_root= (const float*)d_in[10];
    const float* cls1_w = (const float*)d_in[11];
    const float* cls1_b = (const float*)d_in[12];
    const float* cls2_w = (const float*)d_in[13];
    const float* cls2_b = (const float*)d_in[14];
    float* out = (float*)d_out;

    const int nodeTiles = (N_NODES + 63) / 64;   // 1563

    // embedding -> A
    embed_kernel<<<12500, 256>>>(x, emb_w);

    // layer 1: agg in B, h1 written in-place into B
    zero_buf_kernel<<<12500, 256>>>(1);
    edge_kernel<<<100000, 256>>>(ei, ew, 0);
    node_kernel<<<nodeTiles, 256>>>(0, w1_rel, w1_root, b1_rel);

    // layer 2: agg in A (h0 dead), h2 written in-place into A
    zero_buf_kernel<<<12500, 256>>>(0);
    edge_kernel<<<100000, 256>>>(ei, ew, 1);
    node_kernel<<<nodeTiles, 256>>>(1, w2_rel, w2_root, b2_rel);

    // pooling
    zero_pool_kernel<<<129, 256>>>();
    pool_kernel<<<12500, 256>>>(batch);

    // classifier + softmax
    cls_kernel<<<NGRAPH, 64>>>(cls1_w, cls1_b, cls2_w, cls2_b, out);
}